// round 1
// baseline (speedup 1.0000x reference)
#include <cuda_runtime.h>

#define T_STEPS 512
#define BATCH   2048
#define IN_DIM  12
#define E_DIM   15
#define H_DIM   20
#define ROWS_PB 14
#define NTHREADS (ROWS_PB * H_DIM)                  // 280
#define NGRID   ((BATCH + ROWS_PB - 1) / ROWS_PB)   // 147

// ---- packed f32x2 helpers (Blackwell sm_103a) ----
__device__ __forceinline__ unsigned long long pack2(float x, float y) {
    unsigned long long u;
    asm("mov.b64 %0, {%1, %2};" : "=l"(u) : "f"(x), "f"(y));
    return u;
}
__device__ __forceinline__ void fma2(unsigned long long& d,
                                     unsigned long long a,
                                     unsigned long long b) {
    asm("fma.rn.f32x2 %0, %1, %2, %0;" : "+l"(d) : "l"(a), "l"(b));
}
__device__ __forceinline__ float hsum2(unsigned long long u) {
    float x, y;
    asm("mov.b64 {%0, %1}, %2;" : "=f"(x), "=f"(y) : "l"(u));
    return x + y;
}
__device__ __forceinline__ float sigf(float x) {
    return __fdividef(1.0f, 1.0f + __expf(-x));     // EX2 + RCP
}
__device__ __forceinline__ float tanhfast(float x) {
    return __fdividef(2.0f, 1.0f + __expf(-2.0f * x)) - 1.0f;
}

__global__ void __launch_bounds__(NTHREADS, 1)
lstm_tracker_kernel(const float* __restrict__ X,
                    const float* __restrict__ Wemb, const float* __restrict__ bemb,
                    const float* __restrict__ Wih,  const float* __restrict__ bih,
                    const float* __restrict__ Whh,  const float* __restrict__ bhh,
                    const float* __restrict__ Wout, const float* __restrict__ bout,
                    float* __restrict__ out)
{
    __shared__ __align__(16) float s_wemb[E_DIM * IN_DIM];   // 180
    __shared__ __align__(16) float s_wih[4 * H_DIM * E_DIM]; // 1200
    __shared__ __align__(16) float s_wout[3 * H_DIM];        // 60
    __shared__ float s_bout[3];
    __shared__ float s_bemb[E_DIM];
    __shared__ __align__(16) float x_s[2][ROWS_PB][IN_DIM];  // ping-pong x[t]
    __shared__ __align__(16) float h_s[2][ROWS_PB][H_DIM];   // ping-pong h

    const int tid  = threadIdx.x;
    const int row  = tid / H_DIM;        // 0..13 local batch row
    const int k    = tid % H_DIM;        // hidden unit owned by this thread
    const int grow = blockIdx.x * ROWS_PB + row;
    const bool valid = grow < BATCH;

    // ---- cooperative weight staging ----
    for (int i = tid; i < E_DIM * IN_DIM; i += NTHREADS)     s_wemb[i] = Wemb[i];
    for (int i = tid; i < 4 * H_DIM * E_DIM; i += NTHREADS)  s_wih[i]  = Wih[i];
    if (tid < 3 * H_DIM) s_wout[tid] = Wout[tid];
    if (tid < 3)         s_bout[tid] = bout[tid];
    if (tid < E_DIM)     s_bemb[tid] = bemb[tid];
    h_s[0][row][k] = 0.0f;
    h_s[1][row][k] = 0.0f;
    for (int i = tid; i < 2 * ROWS_PB * IN_DIM; i += NTHREADS)
        (&x_s[0][0][0])[i] = 0.0f;
    __syncthreads();

    // ---- per-thread register weights (invariant over t) ----
    // Fused input weights: Wc[r][j] = sum_e Wih[r][e] * Wemb[e][j]   (r = g*20 + k)
    // Fused bias:          bc[r]    = bih[r] + bhh[r] + sum_e Wih[r][e]*bemb[e]
    float bc[4];
    unsigned long long wc[4][IN_DIM / 2];   // 24 x u64
    unsigned long long wh[4][H_DIM / 2];    // 40 x u64
#pragma unroll
    for (int g = 0; g < 4; ++g) {
        const int r = g * H_DIM + k;
        float b = bih[r] + bhh[r];
#pragma unroll
        for (int e = 0; e < E_DIM; ++e) b += s_wih[r * E_DIM + e] * s_bemb[e];
        bc[g] = b;
#pragma unroll
        for (int jj = 0; jj < IN_DIM / 2; ++jj) {
            float c0 = 0.0f, c1 = 0.0f;
#pragma unroll
            for (int e = 0; e < E_DIM; ++e) {
                const float wie = s_wih[r * E_DIM + e];
                c0 += wie * s_wemb[e * IN_DIM + 2 * jj];
                c1 += wie * s_wemb[e * IN_DIM + 2 * jj + 1];
            }
            wc[g][jj] = pack2(c0, c1);
        }
#pragma unroll
        for (int jj = 0; jj < H_DIM / 2; ++jj)
            wh[g][jj] = pack2(Whh[r * H_DIM + 2 * jj], Whh[r * H_DIM + 2 * jj + 1]);
    }

    // ---- preload x[0] ----
    {
        const int xbase = blockIdx.x * (ROWS_PB * IN_DIM);
        if (tid < ROWS_PB * IN_DIM && xbase + tid < BATCH * IN_DIM)
            (&x_s[0][0][0])[tid] = X[xbase + tid];
    }
    float c = 0.0f;
    __syncthreads();

    const long long xstride = (long long)BATCH * IN_DIM;
    int buf = 0;

    for (int t = 0; t < T_STEPS; ++t) {
        // prefetch x[t+1] (issued early; latency hidden under gate math)
        const int xbase = blockIdx.x * (ROWS_PB * IN_DIM);
        const bool pre = (tid < ROWS_PB * IN_DIM) && (t + 1 < T_STEPS) &&
                         (xbase + tid < BATCH * IN_DIM);
        float xpre = 0.0f;
        if (pre) xpre = X[(long long)(t + 1) * xstride + xbase + tid];

        // ---- 4 gates, packed f32x2 dot products ----
        unsigned long long a0 = pack2(bc[0], 0.0f);
        unsigned long long a1 = pack2(bc[1], 0.0f);
        unsigned long long a2 = pack2(bc[2], 0.0f);
        unsigned long long a3 = pack2(bc[3], 0.0f);

        const float2* xr = reinterpret_cast<const float2*>(x_s[buf][row]);
#pragma unroll
        for (int jj = 0; jj < IN_DIM / 2; ++jj) {
            const float2 xv = xr[jj];
            const unsigned long long x2 = pack2(xv.x, xv.y);
            fma2(a0, wc[0][jj], x2); fma2(a1, wc[1][jj], x2);
            fma2(a2, wc[2][jj], x2); fma2(a3, wc[3][jj], x2);
        }
        const float2* hr = reinterpret_cast<const float2*>(h_s[buf][row]);
#pragma unroll
        for (int jj = 0; jj < H_DIM / 2; ++jj) {
            const float2 hv = hr[jj];
            const unsigned long long h2 = pack2(hv.x, hv.y);
            fma2(a0, wh[0][jj], h2); fma2(a1, wh[1][jj], h2);
            fma2(a2, wh[2][jj], h2); fma2(a3, wh[3][jj], h2);
        }

        const float iv = sigf(hsum2(a0));
        const float fv = sigf(hsum2(a1));
        const float gv = tanhfast(hsum2(a2));
        const float ov = sigf(hsum2(a3));
        c = fv * c + iv * gv;
        const float hk = ov * tanhfast(c);
        h_s[buf ^ 1][row][k] = hk;

        // output projection for step t-1 (reads stable h_s[buf] = h_{t-1})
        if (k < 3 && t > 0 && valid) {
            float acc = s_bout[k];
#pragma unroll
            for (int j = 0; j < H_DIM; ++j)
                acc += s_wout[k * H_DIM + j] * h_s[buf][row][j];
            out[(long long)(t - 1) * (BATCH * 3) + grow * 3 + k] = acc;
        }

        if (pre) (&x_s[buf ^ 1][0][0])[tid] = xpre;

        __syncthreads();
        buf ^= 1;
    }

    // final output for t = T-1 (h_{T-1} lives in h_s[buf] after the last flip)
    if (k < 3 && valid) {
        float acc = s_bout[k];
#pragma unroll
        for (int j = 0; j < H_DIM; ++j)
            acc += s_wout[k * H_DIM + j] * h_s[buf][row][j];
        out[(long long)(T_STEPS - 1) * (BATCH * 3) + grow * 3 + k] = acc;
    }
}

extern "C" void kernel_launch(void* const* d_in, const int* in_sizes, int n_in,
                              void* d_out, int out_size) {
    const float* X    = (const float*)d_in[0];
    const float* Wemb = (const float*)d_in[1];
    const float* bemb = (const float*)d_in[2];
    const float* Wih  = (const float*)d_in[3];
    const float* bih  = (const float*)d_in[4];
    const float* Whh  = (const float*)d_in[5];
    const float* bhh  = (const float*)d_in[6];
    const float* Wout = (const float*)d_in[7];
    const float* bout = (const float*)d_in[8];
    float* out = (float*)d_out;

    lstm_tracker_kernel<<<NGRID, NTHREADS>>>(X, Wemb, bemb, Wih, bih,
                                             Whh, bhh, Wout, bout, out);
}